// round 7
// baseline (speedup 1.0000x reference)
#include <cuda_runtime.h>
#include <cuda_bf16.h>

// PLIF neuron scan, T=8. x: [B=32,T=8,S=131072] fp32 -> spikes same shape.
//
// R7: stream-locality restructure. t-loop OUTERMOST; membrane state lives in
// registers across iterations. Per t, each CTA reads one contiguous 16 KB
// chunk and writes one contiguous 16 KB chunk -> 2 sequential DRAM streams
// per CTA at any instant (vs ~16 interleaved 512KB-strided streams before),
// maximizing DRAM row-buffer hits.
//
// Layout: site(k) = chunk*1024 + k*256 + tid, k=0..3 (MLP=4 per iteration).
// Grid: 32 b * 32 chunks = 1024 CTAs x 256 threads.

#define VTH 0.5f
#define S4C 32768u      // float4 per (b,t) plane

__global__ __launch_bounds__(256) void plif_kernel(
    const float4* __restrict__ x,
    const float* __restrict__ w,
    float4* __restrict__ out)
{
    unsigned c = blockIdx.x;            // 0..1023
    unsigned b = c >> 5;                // batch index
    unsigned chunk = c & 31u;           // chunk within plane

    float wv = __ldg(w);
    float tau = 1.0f / (1.0f + __expf(-wv));

    // site offset within a (b,t) plane for k=0
    unsigned soff = chunk * 1024u + threadIdx.x;
    unsigned base = (b << 3) * S4C + soff;   // (b, t=0, site0)

    float4 m[4];
#pragma unroll
    for (int k = 0; k < 4; k++) m[k] = make_float4(0.f, 0.f, 0.f, 0.f);

#pragma unroll
    for (int t = 0; t < 8; t++) {
        const float4* px = x + base + t * S4C;
        float4* po = out + base + t * S4C;

        // 4 independent contiguous-chunk loads -> MLP=4, one read stream.
        float4 xv[4];
#pragma unroll
        for (int k = 0; k < 4; k++) xv[k] = __ldcs(px + k * 256);

#pragma unroll
        for (int k = 0; k < 4; k++) {
            float4 r;

            m[k].x = fmaf(tau, m[k].x, xv[k].x);
            r.x = (m[k].x > VTH) ? 1.0f : 0.0f;
            m[k].x = (m[k].x > VTH) ? 0.0f : m[k].x;

            m[k].y = fmaf(tau, m[k].y, xv[k].y);
            r.y = (m[k].y > VTH) ? 1.0f : 0.0f;
            m[k].y = (m[k].y > VTH) ? 0.0f : m[k].y;

            m[k].z = fmaf(tau, m[k].z, xv[k].z);
            r.z = (m[k].z > VTH) ? 1.0f : 0.0f;
            m[k].z = (m[k].z > VTH) ? 0.0f : m[k].z;

            m[k].w = fmaf(tau, m[k].w, xv[k].w);
            r.w = (m[k].w > VTH) ? 1.0f : 0.0f;
            m[k].w = (m[k].w > VTH) ? 0.0f : m[k].w;

            __stcs(po + k * 256, r);
        }
    }
}

extern "C" void kernel_launch(void* const* d_in, const int* in_sizes, int n_in,
                              void* d_out, int out_size) {
    const float4* x = (const float4*)d_in[0];
    const float* w = (const float*)d_in[1];
    float4* o = (float4*)d_out;

    // 32 batches * 32 chunks = 1024 CTAs, 256 threads each
    plif_kernel<<<1024, 256>>>(x, w, o);
}

// round 8
// speedup vs baseline: 1.0552x; 1.0552x over previous
#include <cuda_runtime.h>
#include <cuda_bf16.h>

// PLIF neuron scan, T=8. x: [B=32,T=8,S=131072] fp32 -> spikes same shape.
// DRAM-ceiling-bound (~5.8 TB/s mixed-stream plateau, invariant under MLP,
// occupancy, cache policy, stream structure).
//
// R8 lever: Blackwell 256-bit global ld/st (v8.f32). Same bytes, half the
// LSU/L1tex transactions per byte. One thread = 8 consecutive floats x 8
// timesteps; all 8 loads front-batched.

#define VTH 0.5f
#define SPLANE 131072u   // floats per (b,t) plane
#define S8C 16384u       // float8 sites per plane
#define S8_SHIFT 14
#define S8_MASK 16383

__device__ __forceinline__ void ld256cs(const float* p, float* v) {
    asm volatile("ld.global.cs.v8.f32 {%0,%1,%2,%3,%4,%5,%6,%7}, [%8];"
                 : "=f"(v[0]), "=f"(v[1]), "=f"(v[2]), "=f"(v[3]),
                   "=f"(v[4]), "=f"(v[5]), "=f"(v[6]), "=f"(v[7])
                 : "l"(p));
}

__device__ __forceinline__ void st256cs(float* p, const float* v) {
    asm volatile("st.global.cs.v8.f32 [%0], {%1,%2,%3,%4,%5,%6,%7,%8};"
                 :: "l"(p),
                    "f"(v[0]), "f"(v[1]), "f"(v[2]), "f"(v[3]),
                    "f"(v[4]), "f"(v[5]), "f"(v[6]), "f"(v[7])
                 : "memory");
}

__global__ __launch_bounds__(256) void plif_kernel(
    const float* __restrict__ x,
    const float* __restrict__ w,
    float* __restrict__ out)
{
    unsigned i = blockIdx.x * 256u + threadIdx.x;   // 0..524287 exact
    unsigned b = i >> S8_SHIFT;
    unsigned s8 = i & S8_MASK;

    float wv = __ldg(w);
    float tau = 1.0f / (1.0f + __expf(-wv));

    unsigned base = (b << 3) * SPLANE + (s8 << 3);  // float offset of (b,0,site)
    const float* px = x + base;
    float* po = out + base;

    // Front-batch all 8 timestep loads (8 x 32B per thread in flight).
    float xv[8][8];
#pragma unroll
    for (int t = 0; t < 8; t++) {
        ld256cs(px + t * SPLANE, xv[t]);
    }

    // Sequential membrane scan over 8 lanes; store each timestep immediately.
    float m[8];
#pragma unroll
    for (int l = 0; l < 8; l++) m[l] = 0.0f;

#pragma unroll
    for (int t = 0; t < 8; t++) {
        float r[8];
#pragma unroll
        for (int l = 0; l < 8; l++) {
            m[l] = fmaf(tau, m[l], xv[t][l]);
            r[l] = (m[l] > VTH) ? 1.0f : 0.0f;
            m[l] = (m[l] > VTH) ? 0.0f : m[l];
        }
        st256cs(po + t * SPLANE, r);
    }
}

extern "C" void kernel_launch(void* const* d_in, const int* in_sizes, int n_in,
                              void* d_out, int out_size) {
    const float* x = (const float*)d_in[0];
    const float* w = (const float*)d_in[1];
    float* o = (float*)d_out;

    // 524,288 float8 sites -> exact 2048 x 256 grid
    plif_kernel<<<2048, 256>>>(x, w, o);
}